// round 1
// baseline (speedup 1.0000x reference)
#include <cuda_runtime.h>
#include <cstdint>

// Problem dims
#define B_    64
#define C_    256
#define H_    32
#define W_    32
#define P_    (B_*H_*W_)        // 65536 pixels
#define NC_   1024              // codebook size
#define NCHW_ (B_*C_*H_*W_)     // 16777216

// Scratch (device globals: allocation-free per harness rules)
__device__ float g_zt[(size_t)P_ * C_];   // z transposed to [P, C]  (64 MB)
__device__ float g_zz[P_];                // ||z||^2 per pixel
__device__ float g_ee[NC_];               // ||e||^2 per code
__device__ int   g_idx[P_];               // argmin indices

// ---------------------------------------------------------------------------
// Kernel 1: NCHW -> [P, C] transpose.  One block per (b,h): tile 256(c) x 32(w)
// ---------------------------------------------------------------------------
__global__ void k_transpose(const float* __restrict__ z) {
    __shared__ float tile[C_][W_ + 1];
    int bh = blockIdx.x;             // 0..2047 : b*32 + h
    int b  = bh >> 5, h = bh & 31;
    int t  = threadIdx.x;            // 256 threads
    int w  = t & 31, cg = t >> 5;    // cg: 0..7

    const float* src = z + ((size_t)b * C_ * H_ + h) * W_;
    #pragma unroll 8
    for (int c = cg; c < C_; c += 8)
        tile[c][w] = src[(size_t)c * H_ * W_ + w];
    __syncthreads();

    float* dst = g_zt + (size_t)bh * W_ * C_;   // pixel p = bh*32 + w
    #pragma unroll 4
    for (int ww = 0; ww < W_; ++ww)
        dst[(size_t)ww * C_ + t] = tile[t][ww];
}

// ---------------------------------------------------------------------------
// Kernel 2/3: row squared-norms (warp per row of 256 floats)
// ---------------------------------------------------------------------------
__global__ void k_rownorm_zt() {
    int warp = (blockIdx.x * blockDim.x + threadIdx.x) >> 5;
    int lane = threadIdx.x & 31;
    if (warp >= P_) return;
    const float* r = g_zt + (size_t)warp * C_;
    float acc = 0.f;
    #pragma unroll
    for (int k = lane; k < C_; k += 32) { float v = r[k]; acc = fmaf(v, v, acc); }
    #pragma unroll
    for (int o = 16; o; o >>= 1) acc += __shfl_xor_sync(0xffffffffu, acc, o);
    if (!lane) g_zz[warp] = acc;
}

__global__ void k_rownorm_cb(const float* __restrict__ cb) {
    int warp = (blockIdx.x * blockDim.x + threadIdx.x) >> 5;
    int lane = threadIdx.x & 31;
    if (warp >= NC_) return;
    const float* r = cb + (size_t)warp * C_;
    float acc = 0.f;
    #pragma unroll
    for (int k = lane; k < C_; k += 32) { float v = r[k]; acc = fmaf(v, v, acc); }
    #pragma unroll
    for (int o = 16; o; o >>= 1) acc += __shfl_xor_sync(0xffffffffu, acc, o);
    if (!lane) g_ee[warp] = acc;
}

// ---------------------------------------------------------------------------
// Kernel 4: fused distance GEMM + argmin.
// Block: 256 threads, tile BM=128 pixels x BN=128 codes, 8x8 register micro-tile,
// loops 8 code-tiles to cover all 1024 codes. Distance assembled with the
// reference's exact fp32 rounding chain: fl(fl(zz+ee) - fl(2*mm)).
// Argmin with first-index tie-break via packed (orderable-dist-bits, idx) min.
// ---------------------------------------------------------------------------
#define BM 128
#define BN 128
#define BK 16

__global__ __launch_bounds__(256) void k_argmin(const float* __restrict__ cb) {
    __shared__ float As[BK][BM];
    __shared__ float Bs[BK][BN];
    __shared__ unsigned long long best[BM];

    int t  = threadIdx.x;
    int tx = t & 15, ty = t >> 4;
    int m0 = blockIdx.x * BM;

    if (t < BM) best[t] = 0xFFFFFFFFFFFFFFFFull;

    float zzr[8];
    #pragma unroll
    for (int i = 0; i < 8; ++i) zzr[i] = g_zz[m0 + ty * 8 + i];
    __syncthreads();

    for (int nt = 0; nt < NC_ / BN; ++nt) {
        int n0 = nt * BN;
        float acc[8][8];
        #pragma unroll
        for (int i = 0; i < 8; ++i)
            #pragma unroll
            for (int j = 0; j < 8; ++j) acc[i][j] = 0.f;

        for (int kt = 0; kt < C_ / BK; ++kt) {
            int k0 = kt * BK;
            // stage A (pixels) and B (codes), transposing [row][k] -> [k][row]
            #pragma unroll
            for (int f = t; f < (BM * BK) / 4; f += 256) {
                int row = f >> 2;
                int kq  = (f & 3) << 2;
                float4 va = *(const float4*)&g_zt[(size_t)(m0 + row) * C_ + k0 + kq];
                As[kq + 0][row] = va.x; As[kq + 1][row] = va.y;
                As[kq + 2][row] = va.z; As[kq + 3][row] = va.w;
                float4 vb = *(const float4*)&cb[(size_t)(n0 + row) * C_ + k0 + kq];
                Bs[kq + 0][row] = vb.x; Bs[kq + 1][row] = vb.y;
                Bs[kq + 2][row] = vb.z; Bs[kq + 3][row] = vb.w;
            }
            __syncthreads();
            #pragma unroll
            for (int kk = 0; kk < BK; ++kk) {
                float a[8], b[8];
                float4 a0 = *(const float4*)&As[kk][ty * 8];
                float4 a1 = *(const float4*)&As[kk][ty * 8 + 4];
                a[0]=a0.x; a[1]=a0.y; a[2]=a0.z; a[3]=a0.w;
                a[4]=a1.x; a[5]=a1.y; a[6]=a1.z; a[7]=a1.w;
                float4 b0 = *(const float4*)&Bs[kk][tx * 8];
                float4 b1 = *(const float4*)&Bs[kk][tx * 8 + 4];
                b[0]=b0.x; b[1]=b0.y; b[2]=b0.z; b[3]=b0.w;
                b[4]=b1.x; b[5]=b1.y; b[6]=b1.z; b[7]=b1.w;
                #pragma unroll
                for (int i = 0; i < 8; ++i)
                    #pragma unroll
                    for (int j = 0; j < 8; ++j)
                        acc[i][j] = fmaf(a[i], b[j], acc[i][j]);
            }
            __syncthreads();
        }

        // epilogue: replicate reference rounding, packed argmin
        float eer[8];
        #pragma unroll
        for (int j = 0; j < 8; ++j) eer[j] = g_ee[n0 + tx * 8 + j];
        #pragma unroll
        for (int i = 0; i < 8; ++i) {
            unsigned long long lb = 0xFFFFFFFFFFFFFFFFull;
            #pragma unroll
            for (int j = 0; j < 8; ++j) {
                float s = __fadd_rn(zzr[i], eer[j]);                       // fl(zz+ee)
                float d = __fsub_rn(s, __fmul_rn(2.0f, acc[i][j]));        // fl(s - fl(2*mm))
                unsigned int bits = __float_as_uint(d);
                // order-preserving map for floats (handles any sign)
                bits = (bits & 0x80000000u) ? ~bits : (bits | 0x80000000u);
                unsigned long long pk =
                    ((unsigned long long)bits << 32) | (unsigned)(n0 + tx * 8 + j);
                lb = (pk < lb) ? pk : lb;
            }
            atomicMin(&best[ty * 8 + i], lb);
        }
    }
    __syncthreads();
    if (t < BM) g_idx[m0 + t] = (int)(best[t] & 0xFFFFFFFFu);
}

// ---------------------------------------------------------------------------
// Kernel 5: gather + write outputs:
//   [0, NCHW)        quantized  (NCHW layout)
//   [NCHW, 2*NCHW)   straight_through (== quantized forward value)
//   [2*NCHW, +P)     encoding_indices as float
// ---------------------------------------------------------------------------
__global__ void k_output(const float* __restrict__ cb, float* __restrict__ out,
                         long long out_size) {
    long long o = (long long)blockIdx.x * blockDim.x + threadIdx.x;
    if (o >= NCHW_) return;
    int w = (int)(o & 31);
    int h = (int)((o >> 5) & 31);
    int c = (int)((o >> 10) & 255);
    int b = (int)(o >> 18);
    int p = (((b << 5) | h) << 5) | w;       // b*1024 + h*32 + w
    int idx = g_idx[p];
    float v = cb[(size_t)idx * C_ + c];
    if (o < out_size) out[o] = v;
    if (NCHW_ + o < out_size) out[NCHW_ + o] = v;
    if (o < P_ && 2LL * NCHW_ + o < out_size)
        out[2LL * NCHW_ + o] = (float)g_idx[(int)o];
}

// ---------------------------------------------------------------------------
extern "C" void kernel_launch(void* const* d_in, const int* in_sizes, int n_in,
                              void* d_out, int out_size) {
    const float* z  = (const float*)d_in[0];   // (64,256,32,32) f32
    const float* cb = (const float*)d_in[1];   // (1024,256) f32
    float* out = (float*)d_out;

    k_transpose<<<B_ * H_, 256>>>(z);
    k_rownorm_zt<<<(P_ * 32 + 255) / 256, 256>>>();
    k_rownorm_cb<<<(NC_ * 32 + 255) / 256, 256>>>(cb);
    k_argmin<<<P_ / BM, 256>>>(cb);
    k_output<<<(NCHW_ + 255) / 256, 256>>>(cb, out, (long long)out_size);
}

// round 5
// speedup vs baseline: 1.4366x; 1.4366x over previous
#include <cuda_runtime.h>
#include <cuda_bf16.h>
#include <cstdint>

#define C_    256
#define P_    65536
#define NC_   1024
#define NCHW_ 16777216

// ---- device scratch -------------------------------------------------------
__device__ __nv_bfloat16 g_ch[NC_ * C_];   // codebook hi bf16, K-major
__device__ __nv_bfloat16 g_cl[NC_ * C_];   // codebook lo bf16
__device__ float g_ee[NC_];
__device__ int   g_idx[P_];
__device__ int   g_nflag;
__device__ int   g_fl[P_];

// ---- k_main smem layout ---------------------------------------------------
// A: 2 mats x 128 rows x 264 bf16 (stride 132 words == 4 mod 32, conflict-free)
#define AW       132
#define OFF_B    135168                 // SB: 2 x 64 x 132 words = 67584 B
#define OFF_EEH  202752                 // 1024 f32
#define OFF_B2   206848                 // 2 x 128 u64
#define OFF_S2   208896                 // 2 x 128 u64
#define SMEM_DYN 210944

// ---------------------------------------------------------------------------
// codebook split + ||e||^2 ; also resets flag counter each call
// ---------------------------------------------------------------------------
__global__ void k_cbsplit(const float* __restrict__ cb) {
    if (blockIdx.x == 0 && threadIdx.x == 0) g_nflag = 0;
    int gw   = (blockIdx.x * blockDim.x + threadIdx.x) >> 5;
    int lane = threadIdx.x & 31;
    if (gw >= NC_) return;
    const float* r = cb + (size_t)gw * C_;
    float acc = 0.f;
    #pragma unroll
    for (int k = lane; k < C_; k += 32) {
        float v = r[k];
        acc = fmaf(v, v, acc);
        __nv_bfloat16 h = __float2bfloat16_rn(v);
        __nv_bfloat16 l = __float2bfloat16_rn(v - __bfloat162float(h));
        g_ch[(size_t)gw * C_ + k] = h;
        g_cl[(size_t)gw * C_ + k] = l;
    }
    #pragma unroll
    for (int o = 16; o; o >>= 1) acc += __shfl_xor_sync(0xffffffffu, acc, o);
    if (!lane) g_ee[gw] = acc;
}

// ---------------------------------------------------------------------------
__device__ __forceinline__ void mma_bf16(float* c, uint32_t a0, uint32_t a1,
                                         uint32_t a2, uint32_t a3,
                                         uint32_t b0, uint32_t b1) {
    asm volatile(
        "mma.sync.aligned.m16n8k16.row.col.f32.bf16.bf16.f32 "
        "{%0,%1,%2,%3}, {%4,%5,%6,%7}, {%8,%9}, {%0,%1,%2,%3};"
        : "+f"(c[0]), "+f"(c[1]), "+f"(c[2]), "+f"(c[3])
        : "r"(a0), "r"(a1), "r"(a2), "r"(a3), "r"(b0), "r"(b1));
}

__device__ __forceinline__ void ins2(unsigned long long& b, unsigned long long& s,
                                     unsigned long long v) {
    if (v < b) { s = b; b = v; }
    else if (v < s) { s = v; }
}

// ---------------------------------------------------------------------------
// main: 128 pixels x 1024 codes per CTA, split-bf16 HMMA; rank by u=ee/2-mm,
// keep top-2, flag near-ties (gap < 6e-5) for exact rescue.
// ---------------------------------------------------------------------------
__global__ __launch_bounds__(256, 1) void k_main(const float* __restrict__ z) {
    extern __shared__ __align__(16) char smem[];
    uint32_t* SA = (uint32_t*)smem;                       // [2][128][132]
    uint32_t* SB = (uint32_t*)(smem + OFF_B);             // [2][64][132]
    float* s_eeh = (float*)(smem + OFF_EEH);
    unsigned long long* s_b2 = (unsigned long long*)(smem + OFF_B2);
    unsigned long long* s_s2 = (unsigned long long*)(smem + OFF_S2);

    const int tid  = threadIdx.x;
    const int lane = tid & 31;
    const int warp = tid >> 5;
    const int g    = lane >> 2;
    const int tc   = lane & 3;
    const int wm   = warp & 3;
    const int wn   = warp >> 2;
    const int m0   = blockIdx.x * 128;

    for (int i = tid; i < NC_; i += 256)
        s_eeh[i] = __fmul_rn(0.5f, g_ee[i]);

    // ---- A: 128 pixels x 256 ch from NCHW z, split to bf16 hi/lo ----
    {
        int m   = tid & 127;
        int cp0 = tid >> 7;
        const float* zb = z + ((size_t)(m0 >> 10) * 256) * 1024 + (m0 & 1023) + m;
        uint32_t* arow_h = SA + (size_t)m * AW;
        uint32_t* arow_l = SA + (size_t)(128 + m) * AW;
        for (int cp = cp0; cp < 128; cp += 2) {
            float v0 = zb[(size_t)(2 * cp) << 10];
            float v1 = zb[(size_t)(2 * cp + 1) << 10];
            __nv_bfloat16 h0 = __float2bfloat16_rn(v0);
            __nv_bfloat16 h1 = __float2bfloat16_rn(v1);
            __nv_bfloat16 l0 = __float2bfloat16_rn(v0 - __bfloat162float(h0));
            __nv_bfloat16 l1 = __float2bfloat16_rn(v1 - __bfloat162float(h1));
            arow_h[cp] = (uint32_t)__bfloat16_as_ushort(h0) |
                         ((uint32_t)__bfloat16_as_ushort(h1) << 16);
            arow_l[cp] = (uint32_t)__bfloat16_as_ushort(l0) |
                         ((uint32_t)__bfloat16_as_ushort(l1) << 16);
        }
    }
    __syncthreads();

    unsigned long long best[4], sec[4];
    #pragma unroll
    for (int j = 0; j < 4; ++j) { best[j] = ~0ULL; sec[j] = ~0ULL; }

    const int apass[3] = { 0, 0, 128 * AW };
    const int bpass[3] = { 0, 64 * AW, 0 };

    for (int nt = 0; nt < 16; ++nt) {
        // ---- stage B tile (64 codes x 256 k, hi+lo) ----
        #pragma unroll
        for (int it = 0; it < 16; ++it) {
            int i   = tid + it * 256;
            int mat = i >> 11;
            int j   = i & 2047;
            int n   = j >> 5;
            int q   = j & 31;
            const __nv_bfloat16* src =
                (mat ? g_cl : g_ch) + (size_t)(nt * 64 + n) * C_ + q * 8;
            uint4 v = *(const uint4*)src;
            *(uint4*)(SB + (size_t)mat * 64 * AW + n * AW + q * 4) = v;
        }
        __syncthreads();

        float acc[2][4][4];
        #pragma unroll
        for (int a = 0; a < 2; ++a)
            #pragma unroll
            for (int b = 0; b < 4; ++b)
                #pragma unroll
                for (int r = 0; r < 4; ++r) acc[a][b][r] = 0.f;

        #pragma unroll
        for (int ps = 0; ps < 3; ++ps) {
            const uint32_t* pA = SA + apass[ps] + (wm * 32 + g) * AW + tc;
            const uint32_t* pB = SB + bpass[ps] + (wn * 32 + g) * AW + tc;
            #pragma unroll 4
            for (int kk = 0; kk < 16; ++kk) {
                const int ko = kk * 8;
                uint32_t b0[4], b1[4];
                #pragma unroll
                for (int ntl = 0; ntl < 4; ++ntl) {
                    const uint32_t* bp = pB + ntl * 8 * AW + ko;
                    b0[ntl] = bp[0];
                    b1[ntl] = bp[4];
                }
                #pragma unroll
                for (int mt = 0; mt < 2; ++mt) {
                    const uint32_t* ap = pA + mt * 16 * AW + ko;
                    uint32_t a0 = ap[0];
                    uint32_t a1 = ap[8 * AW];
                    uint32_t a2 = ap[4];
                    uint32_t a3 = ap[8 * AW + 4];
                    #pragma unroll
                    for (int ntl = 0; ntl < 4; ++ntl)
                        mma_bf16(acc[mt][ntl], a0, a1, a2, a3, b0[ntl], b1[ntl]);
                }
            }
        }
        __syncthreads();

        // ---- epilogue: u = ee/2 - mm, packed top-2 ----
        #pragma unroll
        for (int mt = 0; mt < 2; ++mt)
            #pragma unroll
            for (int ntl = 0; ntl < 4; ++ntl)
                #pragma unroll
                for (int r = 0; r < 4; ++r) {
                    int lr = mt * 2 + (r >> 1);
                    int n  = nt * 64 + wn * 32 + ntl * 8 + tc * 2 + (r & 1);
                    float u = __fsub_rn(s_eeh[n], acc[mt][ntl][r]);
                    uint32_t bits = __float_as_uint(u);
                    bits = (bits & 0x80000000u) ? ~bits : (bits | 0x80000000u);
                    ins2(best[lr], sec[lr],
                         ((unsigned long long)bits << 32) | (unsigned)n);
                }
    }

    // ---- top-2 reduction: tc lanes via shfl, wn warps via smem ----
    #pragma unroll
    for (int j = 0; j < 4; ++j) {
        unsigned long long b = best[j], s = sec[j];
        #pragma unroll
        for (int off = 1; off <= 2; off <<= 1) {
            unsigned long long ob = __shfl_xor_sync(0xffffffffu, b, off);
            unsigned long long os = __shfl_xor_sync(0xffffffffu, s, off);
            ins2(b, s, ob);
            ins2(b, s, os);
        }
        if (tc == 0) {
            int row = wm * 32 + (j >> 1) * 16 + (j & 1) * 8 + g;
            s_b2[wn * 128 + row] = b;
            s_s2[wn * 128 + row] = s;
        }
    }
    __syncthreads();

    if (tid < 128) {
        unsigned long long b = s_b2[tid], s = s_s2[tid];
        ins2(b, s, s_b2[128 + tid]);
        ins2(b, s, s_s2[128 + tid]);
        g_idx[m0 + tid] = (int)(b & 0xFFFFFFFFu);
        uint32_t hb = (uint32_t)(b >> 32), hs = (uint32_t)(s >> 32);
        float ub = __uint_as_float((hb & 0x80000000u) ? (hb & 0x7FFFFFFFu) : ~hb);
        float us = __uint_as_float((hs & 0x80000000u) ? (hs & 0x7FFFFFFFu) : ~hs);
        if (__fsub_rn(us, ub) < 6e-5f) {
            int pos = atomicAdd(&g_nflag, 1);
            g_fl[pos] = m0 + tid;
        }
    }
}

// ---------------------------------------------------------------------------
// rescue: exact fp32 distances for flagged pixels, 8 pixels per cb sweep.
// Replicates reference rounding chain + first-index tie-break.
// ---------------------------------------------------------------------------
__global__ __launch_bounds__(256) void k_rescue(const float* __restrict__ z,
                                                const float* __restrict__ cb) {
    __shared__ float zr[8][257];
    __shared__ float zz8[8];
    __shared__ unsigned long long best8[8];
    __shared__ int pix8[8];
    __shared__ int s_np;

    int tid = threadIdx.x, lane = tid & 31, warp = tid >> 5;

    for (int base = blockIdx.x * 8;; base += gridDim.x * 8) {
        if (tid == 0) {
            int c = g_nflag;
            s_np = c - base;
        }
        __syncthreads();
        int np = s_np;
        if (np <= 0) break;
        if (np > 8) np = 8;

        if (tid < 8) {
            best8[tid] = ~0ULL;
            pix8[tid] = (tid < np) ? g_fl[base + tid] : 0;
        }
        __syncthreads();

        for (int j = 0; j < np; ++j) {
            int p = pix8[j];
            zr[j][tid] = z[(size_t)(p >> 10) * (C_ * 1024) +
                           (size_t)tid * 1024 + (p & 1023)];
        }
        __syncthreads();

        if (warp < np) {
            float a = 0.f;
            #pragma unroll
            for (int k = lane; k < C_; k += 32) {
                float v = zr[warp][k];
                a = fmaf(v, v, a);
            }
            #pragma unroll
            for (int o = 16; o; o >>= 1) a += __shfl_xor_sync(0xffffffffu, a, o);
            if (!lane) zz8[warp] = a;
        }
        __syncthreads();

        for (int n = warp; n < NC_; n += 8) {
            float cv[8];
            const float* cr = cb + (size_t)n * C_;
            #pragma unroll
            for (int jj = 0; jj < 8; ++jj) cv[jj] = cr[lane + 32 * jj];
            float een = __shfl_sync(0xffffffffu, lane == 0 ? g_ee[n] : 0.f, 0);
            for (int j = 0; j < np; ++j) {
                float a = 0.f;
                #pragma unroll
                for (int jj = 0; jj < 8; ++jj)
                    a = fmaf(cv[jj], zr[j][lane + 32 * jj], a);
                #pragma unroll
                for (int o = 16; o; o >>= 1)
                    a += __shfl_xor_sync(0xffffffffu, a, o);
                if (!lane) {
                    float d = __fsub_rn(__fadd_rn(zz8[j], een),
                                        __fmul_rn(2.0f, a));
                    uint32_t bits = __float_as_uint(d);
                    bits = (bits & 0x80000000u) ? ~bits : (bits | 0x80000000u);
                    atomicMin(&best8[j],
                              ((unsigned long long)bits << 32) | (unsigned)n);
                }
            }
        }
        __syncthreads();
        if (tid < np) g_idx[pix8[tid]] = (int)(best8[tid] & 0xFFFFFFFFu);
        __syncthreads();
    }
}

// ---------------------------------------------------------------------------
// outputs via smem transpose: coalesced cb reads + coalesced NCHW writes
// ---------------------------------------------------------------------------
__global__ __launch_bounds__(256) void k_output(const float* __restrict__ cb,
                                                float* __restrict__ out,
                                                long long out_size) {
    __shared__ float tile[256][33];
    __shared__ int idxs[32];
    int bh = blockIdx.x;                     // b*32 + h
    int b = bh >> 5, h = bh & 31;
    int tid = threadIdx.x;

    if (tid < 32) idxs[tid] = g_idx[bh * 32 + tid];
    __syncthreads();

    #pragma unroll 8
    for (int w = 0; w < 32; ++w)
        tile[tid][w] = cb[(size_t)idxs[w] * C_ + tid];
    __syncthreads();

    long long obase = ((long long)b * 256) * 1024 + (long long)h * 32;
    int w = tid & 31;
    #pragma unroll 8
    for (int it = 0; it < 32; ++it) {
        int c = it * 8 + (tid >> 5);
        float v = tile[c][w];
        long long o = obase + (long long)c * 1024 + w;
        if (o < out_size) out[o] = v;
        if (NCHW_ + o < out_size) out[NCHW_ + o] = v;
    }
    if (tid < 32) {
        long long o = 2LL * NCHW_ + bh * 32 + tid;
        if (o < out_size) out[o] = (float)idxs[tid];
    }
}

// ---------------------------------------------------------------------------
extern "C" void kernel_launch(void* const* d_in, const int* in_sizes, int n_in,
                              void* d_out, int out_size) {
    const float* z  = (const float*)d_in[0];   // (64,256,32,32) f32
    const float* cb = (const float*)d_in[1];   // (1024,256) f32
    float* out = (float*)d_out;

    cudaFuncSetAttribute(k_main, cudaFuncAttributeMaxDynamicSharedMemorySize,
                         SMEM_DYN);

    k_cbsplit<<<NC_ / 8, 256>>>(cb);
    k_main<<<P_ / 128, 256, SMEM_DYN>>>(z);
    k_rescue<<<256, 256>>>(z, cb);
    k_output<<<2048, 256>>>(cb, out, (long long)out_size);
}